// round 13
// baseline (speedup 1.0000x reference)
#include <cuda_runtime.h>
#include <cuda_fp16.h>
#include <cstdint>

#define BATCH 32768
#define NVEC  4096
#define EDIM  256
#define KNN   20
#define CAP   64
#define MARGIN 0.5f
#define FILT  0.3f        // 2 x conservative fp16-dot error bound

#define BM 32
#define BN 128
#define PADK 264          // fp16 elems per padded smem row
#define ROWB (PADK * 2)   // 528 bytes

// smem offsets (bytes)
#define SM_A   0          // 32 x 528 = 16896
#define SM_B0  16896      // 128 x 528 = 67584
#define SM_B1  84480
#define SM_MIN 152064     // 32 x u32 (+pad)
#define SMEM_BYTES 152192

#define FINF __int_as_float(0x7F800000)

__device__ __half g_wh[NVEC * EDIM];
__device__ int    g_cnt[BATCH];
__device__ int    g_rec[BATCH * CAP];
__device__ float  g_recv[BATCH * CAP];
__device__ float  g_R[NVEC * EDIM];   // precomputed Gaussian-window results

// ---------------- helpers ----------------
__device__ __forceinline__ uint32_t smem_u32(const void* p) {
    uint32_t a;
    asm("{ .reg .u64 t; cvta.to.shared.u64 t, %1; cvt.u32.u64 %0, t; }" : "=r"(a) : "l"(p));
    return a;
}
__device__ __forceinline__ void cp16(uint32_t dst, const void* src) {
    asm volatile("cp.async.cg.shared.global [%0], [%1], 16;" :: "r"(dst), "l"(src));
}
#define CP_COMMIT() asm volatile("cp.async.commit_group;" ::: "memory")
#define CP_WAIT(n)  asm volatile("cp.async.wait_group %0;" :: "n"(n) : "memory")

__device__ __forceinline__ void ldsm_x4(uint32_t* r, uint32_t addr) {
    asm volatile("ldmatrix.sync.aligned.m8n8.x4.shared.b16 {%0,%1,%2,%3}, [%4];"
                 : "=r"(r[0]), "=r"(r[1]), "=r"(r[2]), "=r"(r[3]) : "r"(addr));
}
__device__ __forceinline__ void mma16816(float* c, const uint32_t* a, const uint32_t* b) {
    asm volatile("mma.sync.aligned.m16n8k16.row.col.f32.f16.f16.f32 "
                 "{%0,%1,%2,%3}, {%4,%5,%6,%7}, {%8,%9}, {%0,%1,%2,%3};"
                 : "+f"(c[0]), "+f"(c[1]), "+f"(c[2]), "+f"(c[3])
                 : "r"(a[0]), "r"(a[1]), "r"(a[2]), "r"(a[3]), "r"(b[0]), "r"(b[1]));
}
__device__ __forceinline__ unsigned sortable(float f) {
    unsigned u = __float_as_uint(f);
    return (u & 0x80000000u) ? ~u : (u | 0x80000000u);
}
__device__ __forceinline__ float unsortable(unsigned u) {
    unsigned b = (u & 0x80000000u) ? (u & 0x7FFFFFFFu) : ~u;
    return __uint_as_float(b);
}

// ---------------- prep + build_R fused (both depend only on W) --------------
// blocks [0, 2048): W fp32->fp16 conversion + zero g_cnt
// blocks [2048, 3072): Gaussian-window table R
__global__ __launch_bounds__(256)
void prep_buildR_kernel(const float* __restrict__ W) {
    const int b = blockIdx.x;
    if (b < 2048) {
        int i = b * 256 + threadIdx.x;
        float2 v = ((const float2*)W)[i & (NVEC * EDIM / 2 - 1)];
        if (i < NVEC * EDIM / 2)
            ((__half2*)g_wh)[i] = __floats2half2_rn(v.x, v.y);
        if (i < BATCH) g_cnt[i] = 0;
    } else {
        const int ix = (b - 2048) * 4 + (threadIdx.x >> 6);
        const int e4 = threadIdx.x & 63;
        const bool left_edge = (ix - KNN) < 0;

        float4 acc = make_float4(0.f, 0.f, 0.f, 0.f);
        float wsum = 0.f;
#pragma unroll
        for (int d = -KNN; d <= KNN; d++) {
            int idx = ix + d;
            bool valid = (idx >= 0) && (idx < NVEC) && (!left_edge || d < KNN);
            if (valid) {
                float g = expf(-0.5f * (float)(d * d));
                wsum += g;
                float4 v = *(const float4*)(W + (long long)idx * EDIM + e4 * 4);
                acc.x = fmaf(g, v.x, acc.x);
                acc.y = fmaf(g, v.y, acc.y);
                acc.z = fmaf(g, v.z, acc.z);
                acc.w = fmaf(g, v.w, acc.w);
            }
        }
        float inv = 1.0f / wsum;
        acc.x *= inv; acc.y *= inv; acc.z *= inv; acc.w *= inv;
        *(float4*)(g_R + (long long)ix * EDIM + e4 * 4) = acc;
    }
}

// ---------------- fp16 GEMM + margin-candidate collection -------------------
// CTA: 32 rows x (loop 32 tiles of 128 cols) — 1024 CTAs -> 98.8% wave util.
// 16 warps: 2(m) x 8(n), warp tile 16x16. Each CTA scans FULL N for its rows,
// so the CTA-shared smem atomicMin threshold stays exact-per-row (R7 lesson).
__global__ __launch_bounds__(512, 1)
void gemm_cand_kernel(const float* __restrict__ x) {
    extern __shared__ char smem[];
    const uint32_t sb = smem_u32(smem);
    unsigned* sMin = (unsigned*)(smem + SM_MIN);

    const int tid  = threadIdx.x;
    const int lane = tid & 31;
    const int wid  = tid >> 5;
    const int wm   = wid >> 3;   // 0..1  (16-row strip)
    const int wn   = wid & 7;    // 0..7  (16-col strip)
    const int m0   = blockIdx.x * BM;

    if (tid < 32) sMin[tid] = 0xFFFFFFFFu;

    // B tile 0 via cp.async (in flight during A conversion below)
    {
        const char* srcB = (const char*)g_wh;
        for (int i = tid; i < 4096; i += 512) {
            int r = i >> 5, g = i & 31;
            cp16(sb + SM_B0 + r * ROWB + g * 16, srcB + r * 512 + g * 16);
        }
    }
    CP_COMMIT();

    // A: 32 rows x 64 float4 = 2048 float4 -> convert fp32->fp16 inline
    {
        const float4* srcA = (const float4*)(x + (size_t)m0 * EDIM);
        for (int i = tid; i < 2048; i += 512) {
            int row = i >> 6, c4 = i & 63;
            float4 v = srcA[row * 64 + c4];
            __half2 h0 = __floats2half2_rn(v.x, v.y);
            __half2 h1 = __floats2half2_rn(v.z, v.w);
            uint32_t u0 = *(uint32_t*)&h0;
            uint32_t u1 = *(uint32_t*)&h1;
            *(uint2*)(smem + SM_A + row * ROWB + c4 * 8) = make_uint2(u0, u1);
        }
    }

    const uint32_t aoff = (uint32_t)((wm * 16 + (lane & 15)) * ROWB + ((lane & 16) ? 16 : 0));
    const uint32_t boff = (uint32_t)((wn * 16 + (lane & 7) + ((lane & 16) ? 8 : 0)) * ROWB +
                                     ((lane & 8) ? 16 : 0));

    for (int nc = 0; nc < NVEC / BN; nc++) {
        if (nc < NVEC / BN - 1) {
            const char* srcB = (const char*)g_wh + (size_t)(nc + 1) * 128 * 512;
            const uint32_t dstB = sb + ((nc & 1) ? SM_B0 : SM_B1);
            for (int i = tid; i < 4096; i += 512) {
                int r = i >> 5, g = i & 31;
                cp16(dstB + r * ROWB + g * 16, srcB + r * 512 + g * 16);
            }
            CP_COMMIT();
            CP_WAIT(1);
        } else {
            CP_WAIT(0);
        }
        __syncthreads();

        const uint32_t sB = sb + ((nc & 1) ? SM_B1 : SM_B0);

        float c[2][4];   // [nt][q]
#pragma unroll
        for (int nt = 0; nt < 2; nt++)
#pragma unroll
            for (int q = 0; q < 4; q++) c[nt][q] = 0.0f;

#pragma unroll
        for (int ks = 0; ks < 16; ks++) {
            uint32_t af[4];
            ldsm_x4(af, sb + SM_A + aoff + ks * 32);
            uint32_t t4[4];
            ldsm_x4(t4, sB + boff + ks * 32);
            uint32_t bf[2][2] = {{t4[0], t4[1]}, {t4[2], t4[3]}};
#pragma unroll
            for (int nt = 0; nt < 2; nt++)
                mma16816(c[nt], af, bf[nt]);
        }

        // ---- per-row running min (CTA-shared) + margin-candidate appends ----
        float rmin[2];
#pragma unroll
        for (int rr = 0; rr < 2; rr++) {
            float m = fminf(c[0][2 * rr], c[0][2 * rr + 1]);
            m = fminf(m, fminf(c[1][2 * rr], c[1][2 * rr + 1]));
            m = fminf(m, __shfl_xor_sync(0xFFFFFFFFu, m, 1));
            m = fminf(m, __shfl_xor_sync(0xFFFFFFFFu, m, 2));
            rmin[rr] = m;
        }
        if ((lane & 3) == 0) {
#pragma unroll
            for (int rr = 0; rr < 2; rr++) {
                int row = wm * 16 + (lane >> 2) + rr * 8;
                atomicMin(&sMin[row], sortable(rmin[rr]));
            }
        }
        __syncthreads();  // also gates next-iter cp.async buffer overwrite

        float thr[2];
#pragma unroll
        for (int rr = 0; rr < 2; rr++) {
            int row = wm * 16 + (lane >> 2) + rr * 8;
            thr[rr] = unsortable(sMin[row]) + MARGIN;
        }
#pragma unroll
        for (int nt = 0; nt < 2; nt++)
#pragma unroll
            for (int q = 0; q < 4; q++) {
                float v = c[nt][q];
                int rr = q >> 1;
                if (v < thr[rr]) {
                    int grow = m0 + wm * 16 + (lane >> 2) + rr * 8;
                    int n = nc * BN + wn * 16 + nt * 8 + 2 * (lane & 3) + (q & 1);
                    int p = atomicAdd(&g_cnt[grow], 1);
                    if (p < CAP) {
                        g_rec[grow * CAP + p] = n;
                        g_recv[grow * CAP + p] = v;
                    }
                }
            }
    }
}

// ---------------- warp-per-row rescore + fused scatter (proven, ~32us) ------
__global__ __launch_bounds__(256)
void rescore_scatter_kernel(const float* __restrict__ x, const float* __restrict__ W,
                            float* __restrict__ out) {
    __shared__ int s_n[8][CAP];
    __shared__ int s_c[8];

    const int w    = threadIdx.x >> 5;
    const int lane = threadIdx.x & 31;
    const int row  = blockIdx.x * 8 + w;
    const int cnt  = g_cnt[row];

    const float4* xr = (const float4*)(x + (size_t)row * EDIM);
    int ix;

    if (cnt <= CAP) {
        float vv[2];
        int   nn[2];
        float lmin = FINF;
#pragma unroll
        for (int j = 0; j < 2; j++) {
            int i = lane + 32 * j;
            if (i < cnt) {
                vv[j] = g_recv[row * CAP + i];
                nn[j] = g_rec[row * CAP + i];
                lmin = fminf(lmin, vv[j]);
            } else { vv[j] = FINF; nn[j] = -1; }
        }
#pragma unroll
        for (int o = 16; o >= 1; o >>= 1)
            lmin = fminf(lmin, __shfl_xor_sync(0xFFFFFFFFu, lmin, o));
        const float thr = lmin + FILT;

        int cs = 0, single = -1;
#pragma unroll
        for (int j = 0; j < 2; j++)
            if (vv[j] <= thr) { cs++; single = nn[j]; }
        int total = cs;
#pragma unroll
        for (int o = 16; o >= 1; o >>= 1)
            total += __shfl_xor_sync(0xFFFFFFFFu, total, o);

        if (total == 1) {
            int cand = (cs == 1) ? single : -1;
#pragma unroll
            for (int o = 16; o >= 1; o >>= 1)
                cand = max(cand, __shfl_xor_sync(0xFFFFFFFFu, cand, o));
            ix = cand;
        } else {
            if (lane == 0) s_c[w] = 0;
            __syncwarp();
#pragma unroll
            for (int j = 0; j < 2; j++)
                if (vv[j] <= thr) {
                    int p = atomicAdd(&s_c[w], 1);
                    s_n[w][p] = nn[j];
                }
            __syncwarp();
            const int nsurv = s_c[w];

            unsigned long long best = 0xFFFFFFFFFFFFFFFFULL;
            for (int base = 0; base < nsurv; base += 32) {
                unsigned long long key = 0xFFFFFFFFFFFFFFFFULL;
                int si = base + lane;
                if (si < nsurv) {
                    int n = s_n[w][si];
                    const float4* wr = (const float4*)(W + (size_t)n * EDIM);
                    float d = 0.0f;
#pragma unroll 4
                    for (int k = 0; k < EDIM / 4; k++) {
                        float4 a = xr[k];
                        float4 b = wr[k];
                        d = fmaf(a.x, b.x, d);
                        d = fmaf(a.y, b.y, d);
                        d = fmaf(a.z, b.z, d);
                        d = fmaf(a.w, b.w, d);
                    }
                    key = ((unsigned long long)sortable(d) << 32) | (unsigned)n;
                }
#pragma unroll
                for (int o = 16; o >= 1; o >>= 1) {
                    unsigned long long ok = __shfl_xor_sync(0xFFFFFFFFu, key, o);
                    if (ok < key) key = ok;
                }
                if (key < best) best = key;
            }
            ix = (int)(best & 0xFFFFFFFFu);
        }
    } else {
        // overflow fallback: exact full scan, lane-per-column, 4-way ILP
        unsigned long long best = 0xFFFFFFFFFFFFFFFFULL;
        for (int g = 0; g < NVEC; g += 128) {
            float d0 = 0.f, d1 = 0.f, d2 = 0.f, d3 = 0.f;
            const float4* w0 = (const float4*)(W + (size_t)(g + lane) * EDIM);
            const float4* w1 = (const float4*)(W + (size_t)(g + 32 + lane) * EDIM);
            const float4* w2 = (const float4*)(W + (size_t)(g + 64 + lane) * EDIM);
            const float4* w3 = (const float4*)(W + (size_t)(g + 96 + lane) * EDIM);
            for (int k = 0; k < EDIM / 4; k++) {
                float4 a = xr[k];
                float4 b0 = w0[k], b1 = w1[k], b2 = w2[k], b3 = w3[k];
                d0 = fmaf(a.x, b0.x, d0); d0 = fmaf(a.y, b0.y, d0);
                d0 = fmaf(a.z, b0.z, d0); d0 = fmaf(a.w, b0.w, d0);
                d1 = fmaf(a.x, b1.x, d1); d1 = fmaf(a.y, b1.y, d1);
                d1 = fmaf(a.z, b1.z, d1); d1 = fmaf(a.w, b1.w, d1);
                d2 = fmaf(a.x, b2.x, d2); d2 = fmaf(a.y, b2.y, d2);
                d2 = fmaf(a.z, b2.z, d2); d2 = fmaf(a.w, b2.w, d2);
                d3 = fmaf(a.x, b3.x, d3); d3 = fmaf(a.y, b3.y, d3);
                d3 = fmaf(a.z, b3.z, d3); d3 = fmaf(a.w, b3.w, d3);
            }
            unsigned long long k0 = ((unsigned long long)sortable(d0) << 32) | (unsigned)(g + lane);
            unsigned long long k1 = ((unsigned long long)sortable(d1) << 32) | (unsigned)(g + 32 + lane);
            unsigned long long k2 = ((unsigned long long)sortable(d2) << 32) | (unsigned)(g + 64 + lane);
            unsigned long long k3 = ((unsigned long long)sortable(d3) << 32) | (unsigned)(g + 96 + lane);
            if (k1 < k0) k0 = k1;
            if (k3 < k2) k2 = k3;
            if (k2 < k0) k0 = k2;
            if (k0 < best) best = k0;
        }
#pragma unroll
        for (int o = 16; o >= 1; o >>= 1) {
            unsigned long long ok = __shfl_xor_sync(0xFFFFFFFFu, best, o);
            if (ok < best) best = ok;
        }
        ix = (int)(best & 0xFFFFFFFFu);
    }

    // fused scatter: out[row] = R[ix]
    const float4* src = (const float4*)(g_R + (size_t)ix * EDIM);
    float4* dst = (float4*)(out + (size_t)row * EDIM);
    dst[lane]      = src[lane];
    dst[lane + 32] = src[lane + 32];
}

// ---------------- host ----------------
extern "C" void kernel_launch(void* const* d_in, const int* in_sizes, int n_in,
                              void* d_out, int out_size) {
    const float* x = (const float*)d_in[0];   // [32768, 256]
    const float* W = (const float*)d_in[1];   // [4096, 256]
    float* out = (float*)d_out;               // [32768, 256]

    prep_buildR_kernel<<<3072, 256>>>(W);

    cudaFuncSetAttribute(gemm_cand_kernel,
                         cudaFuncAttributeMaxDynamicSharedMemorySize, SMEM_BYTES);
    gemm_cand_kernel<<<BATCH / BM, 512, SMEM_BYTES>>>(x);

    rescore_scatter_kernel<<<BATCH / 8, 256>>>(x, W, out);
}

// round 14
// speedup vs baseline: 1.4999x; 1.4999x over previous
#include <cuda_runtime.h>
#include <cuda_fp16.h>
#include <cstdint>

#define BATCH 32768
#define NVEC  4096
#define EDIM  256
#define KNN   20
#define CAP   128
#define MARGIN 0.5f
#define FILT  0.3f        // 2 x conservative fp16-dot error bound

#define BM 128
#define BN 128
#define NQ 4              // N split into quarters
#define TILES_PER_Q 8     // 1024 cols / 128
#define PADK 264          // fp16 elems per padded smem row
#define ROWB (PADK * 2)   // 528 bytes

// smem offsets (bytes)
#define SM_A   0
#define SM_B0  67584
#define SM_B1  135168
#define SM_MIN 202752
#define SMEM_BYTES 203264

#define FINF __int_as_float(0x7F800000)

__device__ __half g_wh[NVEC * EDIM];
__device__ int    g_cnt[BATCH];
__device__ int    g_rec[BATCH * CAP];
__device__ float  g_recv[BATCH * CAP];
__device__ float  g_R[NVEC * EDIM];   // precomputed Gaussian-window results

// ---------------- helpers ----------------
__device__ __forceinline__ uint32_t smem_u32(const void* p) {
    uint32_t a;
    asm("{ .reg .u64 t; cvta.to.shared.u64 t, %1; cvt.u32.u64 %0, t; }" : "=r"(a) : "l"(p));
    return a;
}
__device__ __forceinline__ void cp16(uint32_t dst, const void* src) {
    asm volatile("cp.async.cg.shared.global [%0], [%1], 16;" :: "r"(dst), "l"(src));
}
#define CP_COMMIT() asm volatile("cp.async.commit_group;" ::: "memory")
#define CP_WAIT(n)  asm volatile("cp.async.wait_group %0;" :: "n"(n) : "memory")

__device__ __forceinline__ void ldsm_x4(uint32_t* r, uint32_t addr) {
    asm volatile("ldmatrix.sync.aligned.m8n8.x4.shared.b16 {%0,%1,%2,%3}, [%4];"
                 : "=r"(r[0]), "=r"(r[1]), "=r"(r[2]), "=r"(r[3]) : "r"(addr));
}
__device__ __forceinline__ void mma16816(float* c, const uint32_t* a, const uint32_t* b) {
    asm volatile("mma.sync.aligned.m16n8k16.row.col.f32.f16.f16.f32 "
                 "{%0,%1,%2,%3}, {%4,%5,%6,%7}, {%8,%9}, {%0,%1,%2,%3};"
                 : "+f"(c[0]), "+f"(c[1]), "+f"(c[2]), "+f"(c[3])
                 : "r"(a[0]), "r"(a[1]), "r"(a[2]), "r"(a[3]), "r"(b[0]), "r"(b[1]));
}
__device__ __forceinline__ unsigned sortable(float f) {
    unsigned u = __float_as_uint(f);
    return (u & 0x80000000u) ? ~u : (u | 0x80000000u);
}
__device__ __forceinline__ float unsortable(unsigned u) {
    unsigned b = (u & 0x80000000u) ? (u & 0x7FFFFFFFu) : ~u;
    return __uint_as_float(b);
}

// ---------------- prep + build_R fused (measured 13.2us) --------------------
// blocks [0, 2048): W fp32->fp16 conversion + zero g_cnt
// blocks [2048, 3072): Gaussian-window table R
__global__ __launch_bounds__(256)
void prep_buildR_kernel(const float* __restrict__ W) {
    const int b = blockIdx.x;
    if (b < 2048) {
        int i = b * 256 + threadIdx.x;
        float2 v = ((const float2*)W)[i & (NVEC * EDIM / 2 - 1)];
        if (i < NVEC * EDIM / 2)
            ((__half2*)g_wh)[i] = __floats2half2_rn(v.x, v.y);
        if (i < BATCH) g_cnt[i] = 0;
    } else {
        const int ix = (b - 2048) * 4 + (threadIdx.x >> 6);
        const int e4 = threadIdx.x & 63;
        const bool left_edge = (ix - KNN) < 0;

        float4 acc = make_float4(0.f, 0.f, 0.f, 0.f);
        float wsum = 0.f;
#pragma unroll
        for (int d = -KNN; d <= KNN; d++) {
            int idx = ix + d;
            bool valid = (idx >= 0) && (idx < NVEC) && (!left_edge || d < KNN);
            if (valid) {
                float g = expf(-0.5f * (float)(d * d));
                wsum += g;
                float4 v = *(const float4*)(W + (long long)idx * EDIM + e4 * 4);
                acc.x = fmaf(g, v.x, acc.x);
                acc.y = fmaf(g, v.y, acc.y);
                acc.z = fmaf(g, v.z, acc.z);
                acc.w = fmaf(g, v.w, acc.w);
            }
        }
        float inv = 1.0f / wsum;
        acc.x *= inv; acc.y *= inv; acc.z *= inv; acc.w *= inv;
        *(float4*)(g_R + (long long)ix * EDIM + e4 * 4) = acc;
    }
}

// ---------------- fp16 GEMM + margin-candidate collection -------------------
// Grid 1024 = 4 N-quarters (major) x 256 m-tiles. CTA: 128 rows x 1024 cols
// (8 tiles). R12's proven warp layout: 16 warps 4(m) x 4(n), warp tile 32x32.
// Per-quarter sMin threshold >= global per-row threshold -> superset of the
// global-margin candidate set (argmin provably preserved; FILT < MARGIN).
__global__ __launch_bounds__(512, 1)
void gemm_cand_kernel(const float* __restrict__ x) {
    extern __shared__ char smem[];
    const uint32_t sb = smem_u32(smem);
    unsigned* sMin = (unsigned*)(smem + SM_MIN);

    const int tid  = threadIdx.x;
    const int lane = tid & 31;
    const int wid  = tid >> 5;
    const int wm   = wid >> 2;   // 0..3  (32-row strip)
    const int wn   = wid & 3;    // 0..3  (32-col strip)
    const int mb   = blockIdx.x & 255;
    const int nq   = blockIdx.x >> 8;     // quarter-major for B L2 reuse
    const int m0   = mb * BM;
    const int nc0  = nq * TILES_PER_Q;    // first 128-col chunk of this quarter

    if (tid < 128) sMin[tid] = 0xFFFFFFFFu;

    // B tile nc0 via cp.async (in flight during A conversion below)
    {
        const char* srcB = (const char*)g_wh + (size_t)nc0 * 128 * 512;
        for (int i = tid; i < 4096; i += 512) {
            int r = i >> 5, g = i & 31;
            cp16(sb + SM_B0 + r * ROWB + g * 16, srcB + r * 512 + g * 16);
        }
    }
    CP_COMMIT();

    // A: load fp32 from x, convert to fp16, store into smem layout.
    {
        const float4* srcA = (const float4*)(x + (size_t)m0 * EDIM);
        for (int i = tid; i < 8192; i += 512) {
            int row = i >> 6, c4 = i & 63;
            float4 v = srcA[row * 64 + c4];
            __half2 h0 = __floats2half2_rn(v.x, v.y);
            __half2 h1 = __floats2half2_rn(v.z, v.w);
            uint32_t u0 = *(uint32_t*)&h0;
            uint32_t u1 = *(uint32_t*)&h1;
            *(uint2*)(smem + SM_A + row * ROWB + c4 * 8) = make_uint2(u0, u1);
        }
    }

    const uint32_t aoff = (uint32_t)((wm * 32 + (lane & 15)) * ROWB + ((lane & 16) ? 16 : 0));
    const uint32_t boff = (uint32_t)((wn * 32 + (lane & 7) + ((lane & 16) ? 8 : 0)) * ROWB +
                                     ((lane & 8) ? 16 : 0));

    for (int nc = 0; nc < TILES_PER_Q; nc++) {
        const int nco = nc0 + nc;
        if (nc < TILES_PER_Q - 1) {
            const char* srcB = (const char*)g_wh + (size_t)(nco + 1) * 128 * 512;
            const uint32_t dstB = sb + ((nc & 1) ? SM_B0 : SM_B1);
            for (int i = tid; i < 4096; i += 512) {
                int r = i >> 5, g = i & 31;
                cp16(dstB + r * ROWB + g * 16, srcB + r * 512 + g * 16);
            }
            CP_COMMIT();
            CP_WAIT(1);
        } else {
            CP_WAIT(0);
        }
        __syncthreads();

        const uint32_t sB = sb + ((nc & 1) ? SM_B1 : SM_B0);

        float c[2][4][4];
#pragma unroll
        for (int mt = 0; mt < 2; mt++)
#pragma unroll
            for (int nt = 0; nt < 4; nt++)
#pragma unroll
                for (int q = 0; q < 4; q++) c[mt][nt][q] = 0.0f;

#pragma unroll
        for (int ks = 0; ks < 16; ks++) {
            uint32_t af[2][4];
#pragma unroll
            for (int mt = 0; mt < 2; mt++)
                ldsm_x4(af[mt], sb + SM_A + aoff + mt * (16 * ROWB) + ks * 32);
            uint32_t bf[4][2];
#pragma unroll
            for (int p = 0; p < 2; p++) {
                uint32_t t[4];
                ldsm_x4(t, sB + boff + p * (16 * ROWB) + ks * 32);
                bf[2 * p][0] = t[0]; bf[2 * p][1] = t[1];
                bf[2 * p + 1][0] = t[2]; bf[2 * p + 1][1] = t[3];
            }
#pragma unroll
            for (int mt = 0; mt < 2; mt++)
#pragma unroll
                for (int nt = 0; nt < 4; nt++)
                    mma16816(c[mt][nt], af[mt], bf[nt]);
        }

        // ---- per-row running min (CTA-shared) + margin-candidate appends ----
        float rmin[2][2];
#pragma unroll
        for (int mt = 0; mt < 2; mt++) {
#pragma unroll
            for (int rr = 0; rr < 2; rr++) {
                float m = fminf(c[mt][0][2 * rr], c[mt][0][2 * rr + 1]);
#pragma unroll
                for (int nt = 1; nt < 4; nt++)
                    m = fminf(m, fminf(c[mt][nt][2 * rr], c[mt][nt][2 * rr + 1]));
                m = fminf(m, __shfl_xor_sync(0xFFFFFFFFu, m, 1));
                m = fminf(m, __shfl_xor_sync(0xFFFFFFFFu, m, 2));
                rmin[mt][rr] = m;
            }
        }
        if ((lane & 3) == 0) {
#pragma unroll
            for (int mt = 0; mt < 2; mt++)
#pragma unroll
                for (int rr = 0; rr < 2; rr++) {
                    int row = wm * 32 + mt * 16 + (lane >> 2) + rr * 8;
                    atomicMin(&sMin[row], sortable(rmin[mt][rr]));
                }
        }
        __syncthreads();  // also gates next-iter cp.async buffer overwrite

        float thr[2][2];
#pragma unroll
        for (int mt = 0; mt < 2; mt++)
#pragma unroll
            for (int rr = 0; rr < 2; rr++) {
                int row = wm * 32 + mt * 16 + (lane >> 2) + rr * 8;
                thr[mt][rr] = unsortable(sMin[row]) + MARGIN;
            }
#pragma unroll
        for (int mt = 0; mt < 2; mt++)
#pragma unroll
            for (int nt = 0; nt < 4; nt++)
#pragma unroll
                for (int q = 0; q < 4; q++) {
                    float v = c[mt][nt][q];
                    int rr = q >> 1;
                    if (v < thr[mt][rr]) {
                        int grow = m0 + wm * 32 + mt * 16 + (lane >> 2) + rr * 8;
                        int n = nco * BN + wn * 32 + nt * 8 + 2 * (lane & 3) + (q & 1);
                        int p = atomicAdd(&g_cnt[grow], 1);
                        if (p < CAP) {
                            g_rec[grow * CAP + p] = n;
                            g_recv[grow * CAP + p] = v;
                        }
                    }
                }
    }
}

// ---------------- warp-per-row rescore + fused scatter (R7 CAP=128 variant) -
__global__ __launch_bounds__(256)
void rescore_scatter_kernel(const float* __restrict__ x, const float* __restrict__ W,
                            float* __restrict__ out) {
    __shared__ int s_n[8][CAP];
    __shared__ int s_c[8];

    const int w    = threadIdx.x >> 5;
    const int lane = threadIdx.x & 31;
    const int row  = blockIdx.x * 8 + w;
    const int cnt  = g_cnt[row];

    const float4* xr = (const float4*)(x + (size_t)row * EDIM);
    int ix;

    if (cnt <= CAP) {
        float vv[4];
        int   nn[4];
        float lmin = FINF;
#pragma unroll
        for (int j = 0; j < 4; j++) {
            int i = lane + 32 * j;
            if (i < cnt) {
                vv[j] = g_recv[row * CAP + i];
                nn[j] = g_rec[row * CAP + i];
                lmin = fminf(lmin, vv[j]);
            } else { vv[j] = FINF; nn[j] = -1; }
        }
#pragma unroll
        for (int o = 16; o >= 1; o >>= 1)
            lmin = fminf(lmin, __shfl_xor_sync(0xFFFFFFFFu, lmin, o));
        const float thr = lmin + FILT;

        int cs = 0, single = -1;
#pragma unroll
        for (int j = 0; j < 4; j++)
            if (vv[j] <= thr) { cs++; single = nn[j]; }
        int total = cs;
#pragma unroll
        for (int o = 16; o >= 1; o >>= 1)
            total += __shfl_xor_sync(0xFFFFFFFFu, total, o);

        if (total == 1) {
            int cand = (cs == 1) ? single : -1;
#pragma unroll
            for (int o = 16; o >= 1; o >>= 1)
                cand = max(cand, __shfl_xor_sync(0xFFFFFFFFu, cand, o));
            ix = cand;
        } else {
            if (lane == 0) s_c[w] = 0;
            __syncwarp();
#pragma unroll
            for (int j = 0; j < 4; j++)
                if (vv[j] <= thr) {
                    int p = atomicAdd(&s_c[w], 1);
                    s_n[w][p] = nn[j];
                }
            __syncwarp();
            const int nsurv = s_c[w];

            unsigned long long best = 0xFFFFFFFFFFFFFFFFULL;
            for (int base = 0; base < nsurv; base += 32) {
                unsigned long long key = 0xFFFFFFFFFFFFFFFFULL;
                int si = base + lane;
                if (si < nsurv) {
                    int n = s_n[w][si];
                    const float4* wr = (const float4*)(W + (size_t)n * EDIM);
                    float d = 0.0f;
#pragma unroll 4
                    for (int k = 0; k < EDIM / 4; k++) {
                        float4 a = xr[k];
                        float4 b = wr[k];
                        d = fmaf(a.x, b.x, d);
                        d = fmaf(a.y, b.y, d);
                        d = fmaf(a.z, b.z, d);
                        d = fmaf(a.w, b.w, d);
                    }
                    key = ((unsigned long long)sortable(d) << 32) | (unsigned)n;
                }
#pragma unroll
                for (int o = 16; o >= 1; o >>= 1) {
                    unsigned long long ok = __shfl_xor_sync(0xFFFFFFFFu, key, o);
                    if (ok < key) key = ok;
                }
                if (key < best) best = key;
            }
            ix = (int)(best & 0xFFFFFFFFu);
        }
    } else {
        // overflow fallback: exact full scan, lane-per-column, 4-way ILP
        unsigned long long best = 0xFFFFFFFFFFFFFFFFULL;
        for (int g = 0; g < NVEC; g += 128) {
            float d0 = 0.f, d1 = 0.f, d2 = 0.f, d3 = 0.f;
            const float4* w0 = (const float4*)(W + (size_t)(g + lane) * EDIM);
            const float4* w1 = (const float4*)(W + (size_t)(g + 32 + lane) * EDIM);
            const float4* w2 = (const float4*)(W + (size_t)(g + 64 + lane) * EDIM);
            const float4* w3 = (const float4*)(W + (size_t)(g + 96 + lane) * EDIM);
            for (int k = 0; k < EDIM / 4; k++) {
                float4 a = xr[k];
                float4 b0 = w0[k], b1 = w1[k], b2 = w2[k], b3 = w3[k];
                d0 = fmaf(a.x, b0.x, d0); d0 = fmaf(a.y, b0.y, d0);
                d0 = fmaf(a.z, b0.z, d0); d0 = fmaf(a.w, b0.w, d0);
                d1 = fmaf(a.x, b1.x, d1); d1 = fmaf(a.y, b1.y, d1);
                d1 = fmaf(a.z, b1.z, d1); d1 = fmaf(a.w, b1.w, d1);
                d2 = fmaf(a.x, b2.x, d2); d2 = fmaf(a.y, b2.y, d2);
                d2 = fmaf(a.z, b2.z, d2); d2 = fmaf(a.w, b2.w, d2);
                d3 = fmaf(a.x, b3.x, d3); d3 = fmaf(a.y, b3.y, d3);
                d3 = fmaf(a.w, b3.w, d3); d3 = fmaf(a.z, b3.z, d3);
            }
            unsigned long long k0 = ((unsigned long long)sortable(d0) << 32) | (unsigned)(g + lane);
            unsigned long long k1 = ((unsigned long long)sortable(d1) << 32) | (unsigned)(g + 32 + lane);
            unsigned long long k2 = ((unsigned long long)sortable(d2) << 32) | (unsigned)(g + 64 + lane);
            unsigned long long k3 = ((unsigned long long)sortable(d3) << 32) | (unsigned)(g + 96 + lane);
            if (k1 < k0) k0 = k1;
            if (k3 < k2) k2 = k3;
            if (k2 < k0) k0 = k2;
            if (k0 < best) best = k0;
        }
#pragma unroll
        for (int o = 16; o >= 1; o >>= 1) {
            unsigned long long ok = __shfl_xor_sync(0xFFFFFFFFu, best, o);
            if (ok < best) best = ok;
        }
        ix = (int)(best & 0xFFFFFFFFu);
    }

    // fused scatter: out[row] = R[ix]
    const float4* src = (const float4*)(g_R + (size_t)ix * EDIM);
    float4* dst = (float4*)(out + (size_t)row * EDIM);
    dst[lane]      = src[lane];
    dst[lane + 32] = src[lane + 32];
}

// ---------------- host ----------------
extern "C" void kernel_launch(void* const* d_in, const int* in_sizes, int n_in,
                              void* d_out, int out_size) {
    const float* x = (const float*)d_in[0];   // [32768, 256]
    const float* W = (const float*)d_in[1];   // [4096, 256]
    float* out = (float*)d_out;               // [32768, 256]

    prep_buildR_kernel<<<3072, 256>>>(W);

    cudaFuncSetAttribute(gemm_cand_kernel,
                         cudaFuncAttributeMaxDynamicSharedMemorySize, SMEM_BYTES);
    gemm_cand_kernel<<<(BATCH / BM) * NQ, 512, SMEM_BYTES>>>(x);

    rescore_scatter_kernel<<<BATCH / 8, 256>>>(x, W, out);
}

// round 15
// speedup vs baseline: 1.6075x; 1.0717x over previous
#include <cuda_runtime.h>
#include <cuda_fp16.h>
#include <cstdint>

#define BATCH 32768
#define NVEC  4096
#define EDIM  256
#define KNN   20
#define CAP   64
#define MARGIN 0.5f
#define FILT  0.3f        // 2 x conservative fp16-dot error bound

#define BM 128
#define BN 128
#define PADK 264          // fp16 elems per padded smem row
#define ROWB (PADK * 2)   // 528 bytes

// smem offsets (bytes)
#define SM_A   0
#define SM_B0  67584
#define SM_B1  135168
#define SM_MIN 202752
#define SMEM_BYTES 203264

#define FINF __int_as_float(0x7F800000)

__device__ __half g_wh[NVEC * EDIM];
__device__ int    g_cnt[BATCH];
__device__ int    g_rec[BATCH * CAP];
__device__ float  g_recv[BATCH * CAP];
__device__ float  g_R[NVEC * EDIM];   // precomputed Gaussian-window results

// ---------------- helpers ----------------
__device__ __forceinline__ uint32_t smem_u32(const void* p) {
    uint32_t a;
    asm("{ .reg .u64 t; cvta.to.shared.u64 t, %1; cvt.u32.u64 %0, t; }" : "=r"(a) : "l"(p));
    return a;
}
__device__ __forceinline__ void cp16(uint32_t dst, const void* src) {
    asm volatile("cp.async.cg.shared.global [%0], [%1], 16;" :: "r"(dst), "l"(src));
}
#define CP_COMMIT() asm volatile("cp.async.commit_group;" ::: "memory")
#define CP_WAIT(n)  asm volatile("cp.async.wait_group %0;" :: "n"(n) : "memory")

__device__ __forceinline__ void ldsm_x4(uint32_t* r, uint32_t addr) {
    asm volatile("ldmatrix.sync.aligned.m8n8.x4.shared.b16 {%0,%1,%2,%3}, [%4];"
                 : "=r"(r[0]), "=r"(r[1]), "=r"(r[2]), "=r"(r[3]) : "r"(addr));
}
__device__ __forceinline__ void mma16816(float* c, const uint32_t* a, const uint32_t* b) {
    asm volatile("mma.sync.aligned.m16n8k16.row.col.f32.f16.f16.f32 "
                 "{%0,%1,%2,%3}, {%4,%5,%6,%7}, {%8,%9}, {%0,%1,%2,%3};"
                 : "+f"(c[0]), "+f"(c[1]), "+f"(c[2]), "+f"(c[3])
                 : "r"(a[0]), "r"(a[1]), "r"(a[2]), "r"(a[3]), "r"(b[0]), "r"(b[1]));
}
__device__ __forceinline__ unsigned sortable(float f) {
    unsigned u = __float_as_uint(f);
    return (u & 0x80000000u) ? ~u : (u | 0x80000000u);
}
__device__ __forceinline__ float unsortable(unsigned u) {
    unsigned b = (u & 0x80000000u) ? (u & 0x7FFFFFFFu) : ~u;
    return __uint_as_float(b);
}

// ---------------- prep + build_R fused (measured ~13us) ---------------------
// blocks [0, 2048): W fp32->fp16 conversion + zero g_cnt
// blocks [2048, 3072): Gaussian-window table R
__global__ __launch_bounds__(256)
void prep_buildR_kernel(const float* __restrict__ W) {
    const int b = blockIdx.x;
    if (b < 2048) {
        int i = b * 256 + threadIdx.x;
        float2 v = ((const float2*)W)[i & (NVEC * EDIM / 2 - 1)];
        if (i < NVEC * EDIM / 2)
            ((__half2*)g_wh)[i] = __floats2half2_rn(v.x, v.y);
        if (i < BATCH) g_cnt[i] = 0;
    } else {
        const int ix = (b - 2048) * 4 + (threadIdx.x >> 6);
        const int e4 = threadIdx.x & 63;
        const bool left_edge = (ix - KNN) < 0;

        float4 acc = make_float4(0.f, 0.f, 0.f, 0.f);
        float wsum = 0.f;
#pragma unroll
        for (int d = -KNN; d <= KNN; d++) {
            int idx = ix + d;
            bool valid = (idx >= 0) && (idx < NVEC) && (!left_edge || d < KNN);
            if (valid) {
                float g = expf(-0.5f * (float)(d * d));
                wsum += g;
                float4 v = *(const float4*)(W + (long long)idx * EDIM + e4 * 4);
                acc.x = fmaf(g, v.x, acc.x);
                acc.y = fmaf(g, v.y, acc.y);
                acc.z = fmaf(g, v.z, acc.z);
                acc.w = fmaf(g, v.w, acc.w);
            }
        }
        float inv = 1.0f / wsum;
        acc.x *= inv; acc.y *= inv; acc.z *= inv; acc.w *= inv;
        *(float4*)(g_R + (long long)ix * EDIM + e4 * 4) = acc;
    }
}

// ---------------- fp16 GEMM + margin-candidate collection (R12, proven) -----
// CTA: 128 rows x (loop 32 tiles of 128 cols). 16 warps: 4(m) x 4(n),
// warp tile 32x32 -> 4 warps/SMSP. A converted fp32->fp16 inline (overlapped
// with B tile-0 cp.async). CTA-shared smem atomicMin row threshold (tight).
__global__ __launch_bounds__(512, 1)
void gemm_cand_kernel(const float* __restrict__ x) {
    extern __shared__ char smem[];
    const uint32_t sb = smem_u32(smem);
    unsigned* sMin = (unsigned*)(smem + SM_MIN);

    const int tid  = threadIdx.x;
    const int lane = tid & 31;
    const int wid  = tid >> 5;
    const int wm   = wid >> 2;   // 0..3  (32-row strip)
    const int wn   = wid & 3;    // 0..3  (32-col strip)
    const int m0   = blockIdx.x * BM;

    if (tid < 128) sMin[tid] = 0xFFFFFFFFu;

    // B tile 0 via cp.async (in flight during A conversion below)
    {
        const char* srcB = (const char*)g_wh;
        for (int i = tid; i < 4096; i += 512) {
            int r = i >> 5, g = i & 31;
            cp16(sb + SM_B0 + r * ROWB + g * 16, srcB + r * 512 + g * 16);
        }
    }
    CP_COMMIT();

    // A: load fp32 from x, convert to fp16, store into smem layout.
    // 128 rows x 64 float4/row = 8192 float4; 16 per thread.
    {
        const float4* srcA = (const float4*)(x + (size_t)m0 * EDIM);
        for (int i = tid; i < 8192; i += 512) {
            int row = i >> 6, c4 = i & 63;
            float4 v = srcA[row * 64 + c4];
            __half2 h0 = __floats2half2_rn(v.x, v.y);
            __half2 h1 = __floats2half2_rn(v.z, v.w);
            uint32_t u0 = *(uint32_t*)&h0;
            uint32_t u1 = *(uint32_t*)&h1;
            *(uint2*)(smem + SM_A + row * ROWB + c4 * 8) = make_uint2(u0, u1);
        }
    }

    const uint32_t aoff = (uint32_t)((wm * 32 + (lane & 15)) * ROWB + ((lane & 16) ? 16 : 0));
    const uint32_t boff = (uint32_t)((wn * 32 + (lane & 7) + ((lane & 16) ? 8 : 0)) * ROWB +
                                     ((lane & 8) ? 16 : 0));

    for (int nc = 0; nc < NVEC / BN; nc++) {
        if (nc < NVEC / BN - 1) {
            const char* srcB = (const char*)g_wh + (size_t)(nc + 1) * 128 * 512;
            const uint32_t dstB = sb + ((nc & 1) ? SM_B0 : SM_B1);
            for (int i = tid; i < 4096; i += 512) {
                int r = i >> 5, g = i & 31;
                cp16(dstB + r * ROWB + g * 16, srcB + r * 512 + g * 16);
            }
            CP_COMMIT();
            CP_WAIT(1);
        } else {
            CP_WAIT(0);
        }
        __syncthreads();

        const uint32_t sB = sb + ((nc & 1) ? SM_B1 : SM_B0);

        float c[2][4][4];
#pragma unroll
        for (int mt = 0; mt < 2; mt++)
#pragma unroll
            for (int nt = 0; nt < 4; nt++)
#pragma unroll
                for (int q = 0; q < 4; q++) c[mt][nt][q] = 0.0f;

#pragma unroll
        for (int ks = 0; ks < 16; ks++) {
            uint32_t af[2][4];
#pragma unroll
            for (int mt = 0; mt < 2; mt++)
                ldsm_x4(af[mt], sb + SM_A + aoff + mt * (16 * ROWB) + ks * 32);
            uint32_t bf[4][2];
#pragma unroll
            for (int p = 0; p < 2; p++) {
                uint32_t t[4];
                ldsm_x4(t, sB + boff + p * (16 * ROWB) + ks * 32);
                bf[2 * p][0] = t[0]; bf[2 * p][1] = t[1];
                bf[2 * p + 1][0] = t[2]; bf[2 * p + 1][1] = t[3];
            }
#pragma unroll
            for (int mt = 0; mt < 2; mt++)
#pragma unroll
                for (int nt = 0; nt < 4; nt++)
                    mma16816(c[mt][nt], af[mt], bf[nt]);
        }

        // ---- per-row running min (CTA-shared) + margin-candidate appends ----
        float rmin[2][2];
#pragma unroll
        for (int mt = 0; mt < 2; mt++) {
#pragma unroll
            for (int rr = 0; rr < 2; rr++) {
                float m = fminf(c[mt][0][2 * rr], c[mt][0][2 * rr + 1]);
#pragma unroll
                for (int nt = 1; nt < 4; nt++)
                    m = fminf(m, fminf(c[mt][nt][2 * rr], c[mt][nt][2 * rr + 1]));
                m = fminf(m, __shfl_xor_sync(0xFFFFFFFFu, m, 1));
                m = fminf(m, __shfl_xor_sync(0xFFFFFFFFu, m, 2));
                rmin[mt][rr] = m;
            }
        }
        if ((lane & 3) == 0) {
#pragma unroll
            for (int mt = 0; mt < 2; mt++)
#pragma unroll
                for (int rr = 0; rr < 2; rr++) {
                    int row = wm * 32 + mt * 16 + (lane >> 2) + rr * 8;
                    atomicMin(&sMin[row], sortable(rmin[mt][rr]));
                }
        }
        __syncthreads();  // also gates next-iter cp.async buffer overwrite

        float thr[2][2];
#pragma unroll
        for (int mt = 0; mt < 2; mt++)
#pragma unroll
            for (int rr = 0; rr < 2; rr++) {
                int row = wm * 32 + mt * 16 + (lane >> 2) + rr * 8;
                thr[mt][rr] = unsortable(sMin[row]) + MARGIN;
            }
#pragma unroll
        for (int mt = 0; mt < 2; mt++)
#pragma unroll
            for (int nt = 0; nt < 4; nt++)
#pragma unroll
                for (int q = 0; q < 4; q++) {
                    float v = c[mt][nt][q];
                    int rr = q >> 1;
                    if (v < thr[mt][rr]) {
                        int grow = m0 + wm * 32 + mt * 16 + (lane >> 2) + rr * 8;
                        int n = nc * BN + wn * 32 + nt * 8 + 2 * (lane & 3) + (q & 1);
                        int p = atomicAdd(&g_cnt[grow], 1);
                        if (p < CAP) {
                            g_rec[grow * CAP + p] = n;
                            g_recv[grow * CAP + p] = v;
                        }
                    }
                }
    }
}

// ---------------- warp-per-row rescore + fused scatter (proven, ~32us) ------
__global__ __launch_bounds__(256)
void rescore_scatter_kernel(const float* __restrict__ x, const float* __restrict__ W,
                            float* __restrict__ out) {
    __shared__ int s_n[8][CAP];
    __shared__ int s_c[8];

    const int w    = threadIdx.x >> 5;
    const int lane = threadIdx.x & 31;
    const int row  = blockIdx.x * 8 + w;
    const int cnt  = g_cnt[row];

    const float4* xr = (const float4*)(x + (size_t)row * EDIM);
    int ix;

    if (cnt <= CAP) {
        float vv[2];
        int   nn[2];
        float lmin = FINF;
#pragma unroll
        for (int j = 0; j < 2; j++) {
            int i = lane + 32 * j;
            if (i < cnt) {
                vv[j] = g_recv[row * CAP + i];
                nn[j] = g_rec[row * CAP + i];
                lmin = fminf(lmin, vv[j]);
            } else { vv[j] = FINF; nn[j] = -1; }
        }
#pragma unroll
        for (int o = 16; o >= 1; o >>= 1)
            lmin = fminf(lmin, __shfl_xor_sync(0xFFFFFFFFu, lmin, o));
        const float thr = lmin + FILT;

        int cs = 0, single = -1;
#pragma unroll
        for (int j = 0; j < 2; j++)
            if (vv[j] <= thr) { cs++; single = nn[j]; }
        int total = cs;
#pragma unroll
        for (int o = 16; o >= 1; o >>= 1)
            total += __shfl_xor_sync(0xFFFFFFFFu, total, o);

        if (total == 1) {
            int cand = (cs == 1) ? single : -1;
#pragma unroll
            for (int o = 16; o >= 1; o >>= 1)
                cand = max(cand, __shfl_xor_sync(0xFFFFFFFFu, cand, o));
            ix = cand;
        } else {
            if (lane == 0) s_c[w] = 0;
            __syncwarp();
#pragma unroll
            for (int j = 0; j < 2; j++)
                if (vv[j] <= thr) {
                    int p = atomicAdd(&s_c[w], 1);
                    s_n[w][p] = nn[j];
                }
            __syncwarp();
            const int nsurv = s_c[w];

            unsigned long long best = 0xFFFFFFFFFFFFFFFFULL;
            for (int base = 0; base < nsurv; base += 32) {
                unsigned long long key = 0xFFFFFFFFFFFFFFFFULL;
                int si = base + lane;
                if (si < nsurv) {
                    int n = s_n[w][si];
                    const float4* wr = (const float4*)(W + (size_t)n * EDIM);
                    float d = 0.0f;
#pragma unroll 4
                    for (int k = 0; k < EDIM / 4; k++) {
                        float4 a = xr[k];
                        float4 b = wr[k];
                        d = fmaf(a.x, b.x, d);
                        d = fmaf(a.y, b.y, d);
                        d = fmaf(a.z, b.z, d);
                        d = fmaf(a.w, b.w, d);
                    }
                    key = ((unsigned long long)sortable(d) << 32) | (unsigned)n;
                }
#pragma unroll
                for (int o = 16; o >= 1; o >>= 1) {
                    unsigned long long ok = __shfl_xor_sync(0xFFFFFFFFu, key, o);
                    if (ok < key) key = ok;
                }
                if (key < best) best = key;
            }
            ix = (int)(best & 0xFFFFFFFFu);
        }
    } else {
        // overflow fallback: exact full scan, lane-per-column, 4-way ILP
        unsigned long long best = 0xFFFFFFFFFFFFFFFFULL;
        for (int g = 0; g < NVEC; g += 128) {
            float d0 = 0.f, d1 = 0.f, d2 = 0.f, d3 = 0.f;
            const float4* w0 = (const float4*)(W + (size_t)(g + lane) * EDIM);
            const float4* w1 = (const float4*)(W + (size_t)(g + 32 + lane) * EDIM);
            const float4* w2 = (const float4*)(W + (size_t)(g + 64 + lane) * EDIM);
            const float4* w3 = (const float4*)(W + (size_t)(g + 96 + lane) * EDIM);
            for (int k = 0; k < EDIM / 4; k++) {
                float4 a = xr[k];
                float4 b0 = w0[k], b1 = w1[k], b2 = w2[k], b3 = w3[k];
                d0 = fmaf(a.x, b0.x, d0); d0 = fmaf(a.y, b0.y, d0);
                d0 = fmaf(a.z, b0.z, d0); d0 = fmaf(a.w, b0.w, d0);
                d1 = fmaf(a.x, b1.x, d1); d1 = fmaf(a.y, b1.y, d1);
                d1 = fmaf(a.z, b1.z, d1); d1 = fmaf(a.w, b1.w, d1);
                d2 = fmaf(a.x, b2.x, d2); d2 = fmaf(a.y, b2.y, d2);
                d2 = fmaf(a.z, b2.z, d2); d2 = fmaf(a.w, b2.w, d2);
                d3 = fmaf(a.x, b3.x, d3); d3 = fmaf(a.y, b3.y, d3);
                d3 = fmaf(a.z, b3.z, d3); d3 = fmaf(a.w, b3.w, d3);
            }
            unsigned long long k0 = ((unsigned long long)sortable(d0) << 32) | (unsigned)(g + lane);
            unsigned long long k1 = ((unsigned long long)sortable(d1) << 32) | (unsigned)(g + 32 + lane);
            unsigned long long k2 = ((unsigned long long)sortable(d2) << 32) | (unsigned)(g + 64 + lane);
            unsigned long long k3 = ((unsigned long long)sortable(d3) << 32) | (unsigned)(g + 96 + lane);
            if (k1 < k0) k0 = k1;
            if (k3 < k2) k2 = k3;
            if (k2 < k0) k0 = k2;
            if (k0 < best) best = k0;
        }
#pragma unroll
        for (int o = 16; o >= 1; o >>= 1) {
            unsigned long long ok = __shfl_xor_sync(0xFFFFFFFFu, best, o);
            if (ok < best) best = ok;
        }
        ix = (int)(best & 0xFFFFFFFFu);
    }

    // fused scatter: out[row] = R[ix]
    const float4* src = (const float4*)(g_R + (size_t)ix * EDIM);
    float4* dst = (float4*)(out + (size_t)row * EDIM);
    dst[lane]      = src[lane];
    dst[lane + 32] = src[lane + 32];
}

// ---------------- host ----------------
extern "C" void kernel_launch(void* const* d_in, const int* in_sizes, int n_in,
                              void* d_out, int out_size) {
    const float* x = (const float*)d_in[0];   // [32768, 256]
    const float* W = (const float*)d_in[1];   // [4096, 256]
    float* out = (float*)d_out;               // [32768, 256]

    prep_buildR_kernel<<<3072, 256>>>(W);

    cudaFuncSetAttribute(gemm_cand_kernel,
                         cudaFuncAttributeMaxDynamicSharedMemorySize, SMEM_BYTES);
    gemm_cand_kernel<<<BATCH / BM, 512, SMEM_BYTES>>>(x);

    rescore_scatter_kernel<<<BATCH / 8, 256>>>(x, W, out);
}